// round 14
// baseline (speedup 1.0000x reference)
#include <cuda_runtime.h>
#include <math.h>

#define Bn   64
#define Tn   512
#define NI   64
#define Hn   1024
#define THm  256     // T_HARM
#define TSp  256     // T_SPIKE
#define NCTA 128     // 32 h-groups x 4 batch-groups
#define DT_F 0.042f

#define PAIR_STRIDE 513    // float4 units per hyP pair block (512 + 1 pad)
#define RED_STRIDE  257    // ull units per red pair block (8*32 + 1 pad)

// packed fp32x2 helpers (FFMA2 — only reachable via PTX)
#define FMA2(acc, a, b) asm("fma.rn.f32x2 %0, %1, %2, %0;" : "+l"(acc) : "l"(a), "l"(b))
#define DUP2(d, f)      asm("mov.b64 %0, {%1, %1};" : "=l"(d) : "r"(__float_as_uint(f)))
#define UNPK2(lo, hi, v) asm("mov.b64 {%0, %1}, %2;" : "=f"(lo), "=f"(hi) : "l"(v))

typedef unsigned long long ull;

// fast tanh: 1 - 2/(1 + e^{2x}) via MUFU (abs err ~1e-6; tolerance budget 1e-3)
__device__ __forceinline__ float fast_tanh(float x) {
    float e, r;
    asm("ex2.approx.f32 %0, %1;" : "=f"(e) : "f"(x * 2.88539008f));  // 2*log2(e)
    asm("rcp.approx.f32 %0, %1;" : "=f"(r) : "f"(1.f + e));
    return fmaf(-2.f, r, 1.f);
}

// ---------------- device scratch ----------------
__device__ float g_P[(size_t)Bn * THm * Hn];   // x[:, :256] @ x2h  (64 MB)
__device__ float g_hy[2][Bn * Hn];             // double-buffered recurrent state
__device__ unsigned g_count[4 * 32];           // one counter per group, 128B apart

__device__ __forceinline__ void arrive_release(unsigned* p) {
    asm volatile("red.release.gpu.global.add.u32 [%0], 1;" :: "l"(p) : "memory");
}
__device__ __forceinline__ unsigned ld_acquire(const unsigned* p) {
    unsigned v;
    asm volatile("ld.acquire.gpu.global.u32 %0, [%1];" : "=r"(v) : "l"(p) : "memory");
    return v;
}

// ---------------- init (must reset counters every replay) ----------------
__global__ void init_kernel() {
    int idx = threadIdx.x + blockIdx.x * blockDim.x;
    if (idx < 128) g_count[idx] = 0u;
}

// ---------------- P = x[:, :256] @ x2h  (tiled, FFMA2) ----------------
__global__ void __launch_bounds__(256, 1) p_kernel(
    const float* __restrict__ x, const float* __restrict__ x2h)
{
    extern __shared__ float ps[];
    float* x2hS = ps;             // 32*1024
    float* xS   = ps + 32 * Hn;   // 64*64

    const int tid = threadIdx.x;
    const int tc  = blockIdx.x;
    const int b   = blockIdx.y;

    {
        const float4* src = reinterpret_cast<const float4*>(x + ((size_t)b * Tn + tc * 64) * NI);
        float4* dst = reinterpret_cast<float4*>(xS);
#pragma unroll
        for (int i = 0; i < 4; i++) dst[tid + 256 * i] = src[tid + 256 * i];
    }

    float* Pout = g_P + ((size_t)b * THm + tc * 64) * Hn + tid * 4;
    const ulonglong2* wv = reinterpret_cast<const ulonglong2*>(x2hS);

    for (int kc = 0; kc < 2; kc++) {
        {
            const float4* src = reinterpret_cast<const float4*>(x2h + (size_t)kc * 32 * Hn);
            float4* dst = reinterpret_cast<float4*>(x2hS);
#pragma unroll
            for (int i = 0; i < 32; i++) dst[tid + 256 * i] = src[tid + 256 * i];
        }
        __syncthreads();

        for (int t = 0; t < 64; t++) {
            ull acc0 = 0ull, acc1 = 0ull;
            const float* xr = xS + t * NI + kc * 32;
#pragma unroll 8
            for (int k = 0; k < 32; k++) {
                ull xb; DUP2(xb, xr[k]);
                ulonglong2 w = wv[k * 256 + tid];
                FMA2(acc0, w.x, xb);
                FMA2(acc1, w.y, xb);
            }
            float4 r;
            UNPK2(r.x, r.y, acc0);
            UNPK2(r.z, r.w, acc1);
            float4* po = reinterpret_cast<float4*>(Pout + (size_t)t * Hn);
            if (kc == 1) {
                float4 prev = *po;
                r.x += prev.x; r.y += prev.y; r.z += prev.z; r.w += prev.w;
            }
            *po = r;
        }
        __syncthreads();
    }
}

// ---------------- harmonic scan + hyW + spiking, fused ----------------
// 128 CTAs x 256 threads.  CTA (hb, bb): 32 h x 16 batches.
// GEMM: thread tile 4h x 4b; warp wp owns k range [wp*128, +128).
// Trajectory stores buffered 2 steps in registers (amortize release fencing).
// Tail: hyW reduce in regs, then spike phase inline (same threads).
__global__ void __launch_bounds__(256, 1) harm_kernel(
    const float* __restrict__ h2h, const float* __restrict__ bias,
    const float* __restrict__ gvec, const float* __restrict__ evec,
    float* __restrict__ out)
{
    extern __shared__ float smem[];
    float* Wt  = smem;                         // 32768 floats (Wt2[k][32h])
    float* hyP = smem + 32 * Hn;               // 8 * 513 float4
    float* red = smem + 32 * Hn + 8 * PAIR_STRIDE * 4;  // 8 * 257 ull

    const int tid  = threadIdx.x;
    const int lane = tid & 31;
    const int wp   = tid >> 5;
    const int hb   = blockIdx.x & 31;
    const int bb   = blockIdx.x >> 5;
    const int h    = hb * 32 + lane;
    const int q    = lane & 7;                 // h-quad
    const int g    = lane >> 3;                // b-group
    unsigned* cnt  = &g_count[bb * 32];

    float* hys = out;
    float* hzs = out + (size_t)Bn * Tn * Hn;
    float* us  = out + (size_t)2 * Bn * Tn * Hn;
    float* sp  = us  + (size_t)Bn * TSp * Hn;

    // ---- stage W identity h-major ----
    {
        const int r4 = lane >> 3;
        float4* Wt4 = reinterpret_cast<float4*>(Wt);
#pragma unroll 4
        for (int i2 = 0; i2 < 32; i2++) {
            int k = wp * 128 + i2 * 4 + r4;
            Wt4[k * 8 + q] =
                *(reinterpret_cast<const float4*>(h2h + (size_t)k * Hn + hb * 32) + q);
        }
    }

    const float gy = gvec[h];
    const float ge = evec[h];
    const float bi = bias[h];

    const int b0 = bb * 16 + 2 * wp;
    const int b1 = b0 + 1;
    float hy0 = 0.f, hy1 = 0.f, hz0 = 0.f, hz1 = 0.f;
    float pv0 = __ldcs(&g_P[(size_t)b0 * THm * Hn + h]);
    float pv1 = __ldcs(&g_P[(size_t)b1 * THm * Hn + h]);

    // 2-step register trajectory buffer
    float ty0[2], ty1[2], tz0[2], tz1[2];

    const float4* wrow = reinterpret_cast<const float4*>(Wt) + q;
    const ulonglong2* hvE = reinterpret_cast<const ulonglong2*>(hyP) + (size_t)(2 * g) * PAIR_STRIDE;
    const ulonglong2* hvO = hvE + PAIR_STRIDE;
    ull* redu = reinterpret_cast<ull*>(red);
    const int red_w = wp * 32 + 4 * q;
    __syncthreads();

    for (int t = 0; t < THm; t++) {
        if (t > 0) {
            // warp 0 polls for all 256 warps of this group; others wait at barrier
            if (wp == 0) {
                unsigned want = (unsigned)t << 8;
                while (ld_acquire(cnt) < want) { }
            }
            __syncthreads();

            // ---- stage hy pair wp (pair-interleaved, padded block) ----
            {
                const float* buf = g_hy[t & 1];
                const float4* r0 = reinterpret_cast<const float4*>(buf + (size_t)b0 * Hn);
                const float4* r1 = reinterpret_cast<const float4*>(buf + (size_t)b1 * Hn);
                float4* dst = reinterpret_cast<float4*>(hyP) + (size_t)wp * PAIR_STRIDE;
                float4 ra[8], rc[8];
#pragma unroll
                for (int i = 0; i < 8; i++) {
                    ra[i] = __ldcg(r0 + lane + i * 32);
                    rc[i] = __ldcg(r1 + lane + i * 32);
                }
#pragma unroll
                for (int i = 0; i < 8; i++) {
                    dst[64 * i + lane]      = make_float4(ra[i].x, rc[i].x, ra[i].y, rc[i].y);
                    dst[64 * i + 32 + lane] = make_float4(ra[i].z, rc[i].z, ra[i].w, rc[i].w);
                }
            }
            __syncthreads();

            // ---- GEMM: 4h x 4b thread tile, warp k range [wp*128, +128) ----
            ull acc[4][2];
#pragma unroll
            for (int hh = 0; hh < 4; hh++) { acc[hh][0] = 0ull; acc[hh][1] = 0ull; }
            const int base = wp * 64;
#pragma unroll 4
            for (int t2 = 0; t2 < 32; t2++) {
                ulonglong2 aE = hvE[base + t2];
                ulonglong2 cE = hvE[base + t2 + 32];
                ulonglong2 aO = hvO[base + t2];
                ulonglong2 cO = hvO[base + t2 + 32];
                const int k = (wp * 32 + t2) * 4;
                float4 w0 = wrow[(k + 0) * 8];
                float4 w1 = wrow[(k + 1) * 8];
                float4 w2 = wrow[(k + 2) * 8];
                float4 w3 = wrow[(k + 3) * 8];
#pragma unroll
                for (int hh = 0; hh < 4; hh++) {
                    ull dw0, dw1, dw2, dw3;
                    DUP2(dw0, (&w0.x)[hh]);
                    DUP2(dw1, (&w1.x)[hh]);
                    DUP2(dw2, (&w2.x)[hh]);
                    DUP2(dw3, (&w3.x)[hh]);
                    FMA2(acc[hh][0], aE.x, dw0); FMA2(acc[hh][0], aE.y, dw1);
                    FMA2(acc[hh][0], cE.x, dw2); FMA2(acc[hh][0], cE.y, dw3);
                    FMA2(acc[hh][1], aO.x, dw0); FMA2(acc[hh][1], aO.y, dw1);
                    FMA2(acc[hh][1], cO.x, dw2); FMA2(acc[hh][1], cO.y, dw3);
                }
            }
#pragma unroll
            for (int hh = 0; hh < 4; hh++) {
                redu[(2 * g + 0) * RED_STRIDE + red_w + hh] = acc[hh][0];
                redu[(2 * g + 1) * RED_STRIDE + red_w + hh] = acc[hh][1];
            }
        }
        __syncthreads();

        // ---- update: warp wp owns pair (b0, b1) ----
        float s0 = 0.f, s1 = 0.f;
        if (t > 0) {
            const float2* rv = reinterpret_cast<const float2*>(red);
#pragma unroll
            for (int kw = 0; kw < 8; kw++) {
                float2 v = rv[wp * RED_STRIDE + kw * 32 + lane];
                s0 += v.x; s1 += v.y;
            }
        }
        float th0 = fast_tanh(s0 + pv0 + bi);
        float th1 = fast_tanh(s1 + pv1 + bi);
        hz0 = hz0 + DT_F * (th0 - gy * hy0 - ge * hz0);
        hy0 = hy0 + DT_F * hz0;
        hz1 = hz1 + DT_F * (th1 - gy * hy1 - ge * hz1);
        hy1 = hy1 + DT_F * hz1;

        // state into buffer (t+1)&1, then per-warp release arrival
        float* bufn = g_hy[(t + 1) & 1];
        bufn[(size_t)b0 * Hn + h] = hy0;
        bufn[(size_t)b1 * Hn + h] = hy1;
        if (lane == 0) arrive_release(cnt);

        // next P prefetch (streaming loads first)
        if (t + 1 < THm) {
            pv0 = __ldcs(&g_P[((size_t)b0 * THm + t + 1) * Hn + h]);
            pv1 = __ldcs(&g_P[((size_t)b1 * THm + t + 1) * Hn + h]);
        }

        // trajectory: buffer 2 steps in regs, flush on odd t (halves fence exposure)
        ty0[t & 1] = hy0; ty1[t & 1] = hy1;
        tz0[t & 1] = hz0; tz1[t & 1] = hz1;
        if (t & 1) {
            size_t o0 = ((size_t)b0 * Tn + t - 1) * Hn + h;
            size_t o1 = ((size_t)b1 * Tn + t - 1) * Hn + h;
            __stcs(&hys[o0], ty0[0]);       __stcs(&hys[o1], ty1[0]);
            __stcs(&hzs[o0], tz0[0]);       __stcs(&hzs[o1], tz1[0]);
            __stcs(&hys[o0 + Hn], ty0[1]);  __stcs(&hys[o1 + Hn], ty1[1]);
            __stcs(&hzs[o0 + Hn], tz0[1]);  __stcs(&hzs[o1 + Hn], tz1[1]);
        }
    }

    // ---- hyW = hy_fin @ W (same machinery; result kept in regs) ----
    {
        if (wp == 0) {
            unsigned want = (unsigned)THm << 8;
            while (ld_acquire(cnt) < want) { }
        }
        __syncthreads();
        const float* buf = g_hy[THm & 1];
        const float4* r0 = reinterpret_cast<const float4*>(buf + (size_t)b0 * Hn);
        const float4* r1 = reinterpret_cast<const float4*>(buf + (size_t)b1 * Hn);
        float4* dst = reinterpret_cast<float4*>(hyP) + (size_t)wp * PAIR_STRIDE;
        float4 ra[8], rc[8];
#pragma unroll
        for (int i = 0; i < 8; i++) {
            ra[i] = __ldcg(r0 + lane + i * 32);
            rc[i] = __ldcg(r1 + lane + i * 32);
        }
#pragma unroll
        for (int i = 0; i < 8; i++) {
            dst[64 * i + lane]      = make_float4(ra[i].x, rc[i].x, ra[i].y, rc[i].y);
            dst[64 * i + 32 + lane] = make_float4(ra[i].z, rc[i].z, ra[i].w, rc[i].w);
        }
    }
    __syncthreads();
    {
        ull acc[4][2];
#pragma unroll
        for (int hh = 0; hh < 4; hh++) { acc[hh][0] = 0ull; acc[hh][1] = 0ull; }
        const int base = wp * 64;
#pragma unroll 4
        for (int t2 = 0; t2 < 32; t2++) {
            ulonglong2 aE = hvE[base + t2];
            ulonglong2 cE = hvE[base + t2 + 32];
            ulonglong2 aO = hvO[base + t2];
            ulonglong2 cO = hvO[base + t2 + 32];
            const int k = (wp * 32 + t2) * 4;
            float4 w0 = wrow[(k + 0) * 8];
            float4 w1 = wrow[(k + 1) * 8];
            float4 w2 = wrow[(k + 2) * 8];
            float4 w3 = wrow[(k + 3) * 8];
#pragma unroll
            for (int hh = 0; hh < 4; hh++) {
                ull dw0, dw1, dw2, dw3;
                DUP2(dw0, (&w0.x)[hh]);
                DUP2(dw1, (&w1.x)[hh]);
                DUP2(dw2, (&w2.x)[hh]);
                DUP2(dw3, (&w3.x)[hh]);
                FMA2(acc[hh][0], aE.x, dw0); FMA2(acc[hh][0], aE.y, dw1);
                FMA2(acc[hh][0], cE.x, dw2); FMA2(acc[hh][0], cE.y, dw3);
                FMA2(acc[hh][1], aO.x, dw0); FMA2(acc[hh][1], aO.y, dw1);
                FMA2(acc[hh][1], cO.x, dw2); FMA2(acc[hh][1], cO.y, dw3);
            }
        }
#pragma unroll
        for (int hh = 0; hh < 4; hh++) {
            redu[(2 * g + 0) * RED_STRIDE + red_w + hh] = acc[hh][0];
            redu[(2 * g + 1) * RED_STRIDE + red_w + hh] = acc[hh][1];
        }
    }
    __syncthreads();
    float hyw0 = 0.f, hyw1 = 0.f;
    {
        const float2* rv = reinterpret_cast<const float2*>(red);
#pragma unroll
        for (int kw = 0; kw < 8; kw++) {
            float2 v = rv[wp * RED_STRIDE + kw * 32 + lane];
            hyw0 += v.x; hyw1 += v.y;
        }
    }

    // ---- spiking phase + tail broadcast, inline (thread owns b0,b1 at column h) ----
    {
        float u0 = 0.f, u1 = 0.f;
        const float kk = 0.025f * 0.042f;
        const float* P0 = g_P + (size_t)b0 * THm * Hn + h;
        const float* P1 = g_P + (size_t)b1 * THm * Hn + h;
        size_t o_us0 = (size_t)b0 * TSp * Hn + h;
        size_t o_us1 = (size_t)b1 * TSp * Hn + h;
        size_t o_hy0 = ((size_t)b0 * Tn + THm) * Hn + h;
        size_t o_hy1 = ((size_t)b1 * Tn + THm) * Hn + h;
#pragma unroll 4
        for (int t = 0; t < TSp; t++) {
            float s0v = (u0 > 0.008f) ? 1.f : 0.f;  if (s0v != 0.f) u0 = 0.001f;
            float s1v = (u1 > 0.008f) ? 1.f : 0.f;  if (s1v != 0.f) u1 = 0.001f;
            float p0 = __ldcs(P0 + (size_t)t * Hn);
            float p1 = __ldcs(P1 + (size_t)t * Hn);
            u0 += (-u0 + hyw0 + p0) * kk;
            u1 += (-u1 + hyw1 + p1) * kk;
            __stcs(&us[o_us0], u0);   __stcs(&us[o_us1], u1);
            __stcs(&sp[o_us0], s0v);  __stcs(&sp[o_us1], s1v);
            __stcs(&hys[o_hy0], hy0); __stcs(&hys[o_hy1], hy1);
            __stcs(&hzs[o_hy0], hz0); __stcs(&hzs[o_hy1], hz1);
            o_us0 += Hn; o_us1 += Hn; o_hy0 += Hn; o_hy1 += Hn;
        }
    }
}

// ---------------- launch ----------------
extern "C" void kernel_launch(void* const* d_in, const int* in_sizes, int n_in,
                              void* d_out, int out_size) {
    const float* x    = (const float*)d_in[0];
    const float* x2h  = (const float*)d_in[1];
    const float* h2h  = (const float*)d_in[2];
    const float* bias = (const float*)d_in[3];
    const float* gvec = (const float*)d_in[4];
    const float* evec = (const float*)d_in[5];
    float* out = (float*)d_out;

    const int harm_smem = (32 * Hn) * 4 + 8 * PAIR_STRIDE * 16 + 8 * RED_STRIDE * 8;
    const int p_smem    = (32 * Hn + 64 * NI) * (int)sizeof(float);  // 144 KB
    cudaFuncSetAttribute(harm_kernel, cudaFuncAttributeMaxDynamicSharedMemorySize, harm_smem);
    cudaFuncSetAttribute(p_kernel, cudaFuncAttributeMaxDynamicSharedMemorySize, p_smem);

    init_kernel<<<1, 128>>>();
    p_kernel<<<dim3(4, 64), 256, p_smem>>>(x, x2h);
    harm_kernel<<<NCTA, 256, harm_smem>>>(h2h, bias, gvec, evec, out);
}

// round 15
// speedup vs baseline: 1.5250x; 1.5250x over previous
#include <cuda_runtime.h>
#include <math.h>

#define Bn   64
#define Tn   512
#define NI   64
#define Hn   1024
#define THm  256     // T_HARM
#define TSp  256     // T_SPIKE
#define NCTA 128     // 32 h-groups x 4 batch-groups
#define DT_F 0.042f

#define PAIR_STRIDE 513    // float4 units per hyP pair block (512 + 1 pad)
#define RED_STRIDE  257    // ull units per red pair block (8*32 + 1 pad)

// packed fp32x2 helpers (FFMA2 — only reachable via PTX)
#define FMA2(acc, a, b) asm("fma.rn.f32x2 %0, %1, %2, %0;" : "+l"(acc) : "l"(a), "l"(b))
#define DUP2(d, f)      asm("mov.b64 %0, {%1, %1};" : "=l"(d) : "r"(__float_as_uint(f)))
#define UNPK2(lo, hi, v) asm("mov.b64 {%0, %1}, %2;" : "=f"(lo), "=f"(hi) : "l"(v))

typedef unsigned long long ull;

// fast tanh: 1 - 2/(1 + e^{2x}) via MUFU (abs err ~1e-6; tolerance budget 1e-3)
__device__ __forceinline__ float fast_tanh(float x) {
    float e, r;
    asm("ex2.approx.f32 %0, %1;" : "=f"(e) : "f"(x * 2.88539008f));  // 2*log2(e)
    asm("rcp.approx.f32 %0, %1;" : "=f"(r) : "f"(1.f + e));
    return fmaf(-2.f, r, 1.f);
}

// ---------------- device scratch ----------------
__device__ float g_P[(size_t)Bn * THm * Hn];   // x[:, :256] @ x2h  (64 MB)
__device__ float g_hy[2][Bn * Hn];             // double-buffered recurrent state
__device__ float g_hyfin[Bn * Hn];
__device__ float g_hzfin[Bn * Hn];
__device__ float g_hyW[Bn * Hn];
__device__ unsigned g_count[4 * 32];           // one counter per group, 128B apart

__device__ __forceinline__ void arrive_release(unsigned* p) {
    asm volatile("red.release.gpu.global.add.u32 [%0], 1;" :: "l"(p) : "memory");
}
__device__ __forceinline__ unsigned ld_acquire(const unsigned* p) {
    unsigned v;
    asm volatile("ld.acquire.gpu.global.u32 %0, [%1];" : "=r"(v) : "l"(p) : "memory");
    return v;
}

// ---------------- init (must reset counters every replay) ----------------
__global__ void init_kernel() {
    int idx = threadIdx.x + blockIdx.x * blockDim.x;
    if (idx < 128) g_count[idx] = 0u;
}

// ---------------- P = x[:, :256] @ x2h  (tiled, FFMA2) ----------------
__global__ void __launch_bounds__(256, 1) p_kernel(
    const float* __restrict__ x, const float* __restrict__ x2h)
{
    extern __shared__ float ps[];
    float* x2hS = ps;             // 32*1024
    float* xS   = ps + 32 * Hn;   // 64*64

    const int tid = threadIdx.x;
    const int tc  = blockIdx.x;
    const int b   = blockIdx.y;

    {
        const float4* src = reinterpret_cast<const float4*>(x + ((size_t)b * Tn + tc * 64) * NI);
        float4* dst = reinterpret_cast<float4*>(xS);
#pragma unroll
        for (int i = 0; i < 4; i++) dst[tid + 256 * i] = src[tid + 256 * i];
    }

    float* Pout = g_P + ((size_t)b * THm + tc * 64) * Hn + tid * 4;
    const ulonglong2* wv = reinterpret_cast<const ulonglong2*>(x2hS);

    for (int kc = 0; kc < 2; kc++) {
        {
            const float4* src = reinterpret_cast<const float4*>(x2h + (size_t)kc * 32 * Hn);
            float4* dst = reinterpret_cast<float4*>(x2hS);
#pragma unroll
            for (int i = 0; i < 32; i++) dst[tid + 256 * i] = src[tid + 256 * i];
        }
        __syncthreads();

        for (int t = 0; t < 64; t++) {
            ull acc0 = 0ull, acc1 = 0ull;
            const float* xr = xS + t * NI + kc * 32;
#pragma unroll 8
            for (int k = 0; k < 32; k++) {
                ull xb; DUP2(xb, xr[k]);
                ulonglong2 w = wv[k * 256 + tid];
                FMA2(acc0, w.x, xb);
                FMA2(acc1, w.y, xb);
            }
            float4 r;
            UNPK2(r.x, r.y, acc0);
            UNPK2(r.z, r.w, acc1);
            float4* po = reinterpret_cast<float4*>(Pout + (size_t)t * Hn);
            if (kc == 1) {
                float4 prev = *po;
                r.x += prev.x; r.y += prev.y; r.z += prev.z; r.w += prev.w;
            }
            *po = r;
        }
        __syncthreads();
    }
}

// ---------------- harmonic persistent scan (full range, merged) ----------------
// 128 CTAs x 256 threads.  CTA (hb, bb): 32 h x 16 batches.
// GEMM: thread tile 4h x 4b: lane -> (q = lane&7 h-quad, g = lane>>3 b-group);
//       warp wp owns k range [wp*128, wp*128+128).
// Wt2[k][h] identity h-major (128KB).  hyP pair-interleaved, pair stride 513 float4.
// Update: warp wp owns pair wp.  Barrier: per-group monotonic counter, warp 0 polls.
__global__ void __launch_bounds__(256, 1) harm_kernel(
    const float* __restrict__ h2h, const float* __restrict__ bias,
    const float* __restrict__ gvec, const float* __restrict__ evec,
    float* __restrict__ hys, float* __restrict__ hzs)
{
    extern __shared__ float smem[];
    float* Wt  = smem;                         // 32768 floats (Wt2[k][32h])
    float* hyP = smem + 32 * Hn;               // 8 * 513 float4
    float* red = smem + 32 * Hn + 8 * PAIR_STRIDE * 4;  // 8 * 257 ull

    const int tid  = threadIdx.x;
    const int lane = tid & 31;
    const int wp   = tid >> 5;
    const int hb   = blockIdx.x & 31;
    const int bb   = blockIdx.x >> 5;
    const int h    = hb * 32 + lane;
    const int q    = lane & 7;                 // h-quad
    const int g    = lane >> 3;                // b-group
    unsigned* cnt  = &g_count[bb * 32];

    // ---- stage W identity h-major: Wt2[k*32 .. k*32+31] = h2h[k][hb*32 ..+31] ----
    {
        const int r4 = lane >> 3;
        float4* Wt4 = reinterpret_cast<float4*>(Wt);
#pragma unroll 4
        for (int i2 = 0; i2 < 32; i2++) {
            int k = wp * 128 + i2 * 4 + r4;
            Wt4[k * 8 + q] =
                *(reinterpret_cast<const float4*>(h2h + (size_t)k * Hn + hb * 32) + q);
        }
    }

    const float gy = gvec[h];
    const float ge = evec[h];
    const float bi = bias[h];

    const int b0 = bb * 16 + 2 * wp;
    const int b1 = b0 + 1;
    float hy0 = 0.f, hy1 = 0.f, hz0 = 0.f, hz1 = 0.f;
    float pv0 = __ldcs(&g_P[(size_t)b0 * THm * Hn + h]);
    float pv1 = __ldcs(&g_P[(size_t)b1 * THm * Hn + h]);

    const float4* wrow = reinterpret_cast<const float4*>(Wt) + q;             // + k*8
    const ulonglong2* hvE = reinterpret_cast<const ulonglong2*>(hyP) + (size_t)(2 * g) * PAIR_STRIDE;
    const ulonglong2* hvO = hvE + PAIR_STRIDE;
    ull* redu = reinterpret_cast<ull*>(red);
    const int red_w = wp * 32 + 4 * q;        // + hh, within pair block
    __syncthreads();

    for (int t = 0; t < THm; t++) {
        if (t > 0) {
            // warp 0 polls for all 256 warps of this group; others wait at barrier
            if (wp == 0) {
                unsigned want = (unsigned)t << 8;
                while (ld_acquire(cnt) < want) { }
            }
            __syncthreads();

            // ---- stage hy pair wp (pair-interleaved, padded block) ----
            {
                const float* buf = g_hy[t & 1];
                const float4* r0 = reinterpret_cast<const float4*>(buf + (size_t)b0 * Hn);
                const float4* r1 = reinterpret_cast<const float4*>(buf + (size_t)b1 * Hn);
                float4* dst = reinterpret_cast<float4*>(hyP) + (size_t)wp * PAIR_STRIDE;
                float4 ra[8], rc[8];
#pragma unroll
                for (int i = 0; i < 8; i++) {
                    ra[i] = __ldcg(r0 + lane + i * 32);
                    rc[i] = __ldcg(r1 + lane + i * 32);
                }
#pragma unroll
                for (int i = 0; i < 8; i++) {
                    dst[64 * i + lane]      = make_float4(ra[i].x, rc[i].x, ra[i].y, rc[i].y);
                    dst[64 * i + 32 + lane] = make_float4(ra[i].z, rc[i].z, ra[i].w, rc[i].w);
                }
            }
            __syncthreads();

            // ---- GEMM: 4h x 4b thread tile, warp k range [wp*128, +128) ----
            ull acc[4][2];
#pragma unroll
            for (int hh = 0; hh < 4; hh++) { acc[hh][0] = 0ull; acc[hh][1] = 0ull; }
            const int base = wp * 64;
#pragma unroll 4
            for (int t2 = 0; t2 < 32; t2++) {
                ulonglong2 aE = hvE[base + t2];        // pair 2g,   k=4k4,4k4+1
                ulonglong2 cE = hvE[base + t2 + 32];   // pair 2g,   k=4k4+2,+3
                ulonglong2 aO = hvO[base + t2];        // pair 2g+1
                ulonglong2 cO = hvO[base + t2 + 32];
                const int k = (wp * 32 + t2) * 4;
                float4 w0 = wrow[(k + 0) * 8];
                float4 w1 = wrow[(k + 1) * 8];
                float4 w2 = wrow[(k + 2) * 8];
                float4 w3 = wrow[(k + 3) * 8];
#pragma unroll
                for (int hh = 0; hh < 4; hh++) {
                    ull dw0, dw1, dw2, dw3;
                    DUP2(dw0, (&w0.x)[hh]);
                    DUP2(dw1, (&w1.x)[hh]);
                    DUP2(dw2, (&w2.x)[hh]);
                    DUP2(dw3, (&w3.x)[hh]);
                    FMA2(acc[hh][0], aE.x, dw0); FMA2(acc[hh][0], aE.y, dw1);
                    FMA2(acc[hh][0], cE.x, dw2); FMA2(acc[hh][0], cE.y, dw3);
                    FMA2(acc[hh][1], aO.x, dw0); FMA2(acc[hh][1], aO.y, dw1);
                    FMA2(acc[hh][1], cO.x, dw2); FMA2(acc[hh][1], cO.y, dw3);
                }
            }
#pragma unroll
            for (int hh = 0; hh < 4; hh++) {
                redu[(2 * g + 0) * RED_STRIDE + red_w + hh] = acc[hh][0];
                redu[(2 * g + 1) * RED_STRIDE + red_w + hh] = acc[hh][1];
            }
        }
        __syncthreads();

        // ---- update: warp wp owns pair (b0, b1) ----
        float s0 = 0.f, s1 = 0.f;
        if (t > 0) {
            const float2* rv = reinterpret_cast<const float2*>(red);
#pragma unroll
            for (int kw = 0; kw < 8; kw++) {
                float2 v = rv[wp * RED_STRIDE + kw * 32 + lane];
                s0 += v.x; s1 += v.y;
            }
        }
        float th0 = fast_tanh(s0 + pv0 + bi);
        float th1 = fast_tanh(s1 + pv1 + bi);
        hz0 = hz0 + DT_F * (th0 - gy * hy0 - ge * hz0);
        hy0 = hy0 + DT_F * hz0;
        hz1 = hz1 + DT_F * (th1 - gy * hy1 - ge * hz1);
        hy1 = hy1 + DT_F * hz1;

        // state into buffer (t+1)&1, then per-warp release arrival
        float* bufn = g_hy[(t + 1) & 1];
        bufn[(size_t)b0 * Hn + h] = hy0;
        bufn[(size_t)b1 * Hn + h] = hy1;
        if (lane == 0) arrive_release(cnt);

        // next P prefetch (streaming loads first), then streaming trajectory stores
        if (t + 1 < THm) {
            pv0 = __ldcs(&g_P[((size_t)b0 * THm + t + 1) * Hn + h]);
            pv1 = __ldcs(&g_P[((size_t)b1 * THm + t + 1) * Hn + h]);
        }
        __stcs(&hys[((size_t)b0 * Tn + t) * Hn + h], hy0);
        __stcs(&hys[((size_t)b1 * Tn + t) * Hn + h], hy1);
        __stcs(&hzs[((size_t)b0 * Tn + t) * Hn + h], hz0);
        __stcs(&hzs[((size_t)b1 * Tn + t) * Hn + h], hz1);
    }

    // ---- finals ----
    g_hyfin[(size_t)b0 * Hn + h] = hy0;
    g_hyfin[(size_t)b1 * Hn + h] = hy1;
    g_hzfin[(size_t)b0 * Hn + h] = hz0;
    g_hzfin[(size_t)b1 * Hn + h] = hz1;

    // ---- hyW = hy_fin @ W ----
    {
        if (wp == 0) {
            unsigned want = (unsigned)THm << 8;
            while (ld_acquire(cnt) < want) { }
        }
        __syncthreads();
        const float* buf = g_hy[THm & 1];
        const float4* r0 = reinterpret_cast<const float4*>(buf + (size_t)b0 * Hn);
        const float4* r1 = reinterpret_cast<const float4*>(buf + (size_t)b1 * Hn);
        float4* dst = reinterpret_cast<float4*>(hyP) + (size_t)wp * PAIR_STRIDE;
        float4 ra[8], rc[8];
#pragma unroll
        for (int i = 0; i < 8; i++) {
            ra[i] = __ldcg(r0 + lane + i * 32);
            rc[i] = __ldcg(r1 + lane + i * 32);
        }
#pragma unroll
        for (int i = 0; i < 8; i++) {
            dst[64 * i + lane]      = make_float4(ra[i].x, rc[i].x, ra[i].y, rc[i].y);
            dst[64 * i + 32 + lane] = make_float4(ra[i].z, rc[i].z, ra[i].w, rc[i].w);
        }
    }
    __syncthreads();
    {
        ull acc[4][2];
#pragma unroll
        for (int hh = 0; hh < 4; hh++) { acc[hh][0] = 0ull; acc[hh][1] = 0ull; }
        const int base = wp * 64;
#pragma unroll 4
        for (int t2 = 0; t2 < 32; t2++) {
            ulonglong2 aE = hvE[base + t2];
            ulonglong2 cE = hvE[base + t2 + 32];
            ulonglong2 aO = hvO[base + t2];
            ulonglong2 cO = hvO[base + t2 + 32];
            const int k = (wp * 32 + t2) * 4;
            float4 w0 = wrow[(k + 0) * 8];
            float4 w1 = wrow[(k + 1) * 8];
            float4 w2 = wrow[(k + 2) * 8];
            float4 w3 = wrow[(k + 3) * 8];
#pragma unroll
            for (int hh = 0; hh < 4; hh++) {
                ull dw0, dw1, dw2, dw3;
                DUP2(dw0, (&w0.x)[hh]);
                DUP2(dw1, (&w1.x)[hh]);
                DUP2(dw2, (&w2.x)[hh]);
                DUP2(dw3, (&w3.x)[hh]);
                FMA2(acc[hh][0], aE.x, dw0); FMA2(acc[hh][0], aE.y, dw1);
                FMA2(acc[hh][0], cE.x, dw2); FMA2(acc[hh][0], cE.y, dw3);
                FMA2(acc[hh][1], aO.x, dw0); FMA2(acc[hh][1], aO.y, dw1);
                FMA2(acc[hh][1], cO.x, dw2); FMA2(acc[hh][1], cO.y, dw3);
            }
        }
#pragma unroll
        for (int hh = 0; hh < 4; hh++) {
            redu[(2 * g + 0) * RED_STRIDE + red_w + hh] = acc[hh][0];
            redu[(2 * g + 1) * RED_STRIDE + red_w + hh] = acc[hh][1];
        }
    }
    __syncthreads();
    {
        const float2* rv = reinterpret_cast<const float2*>(red);
        float s0 = 0.f, s1 = 0.f;
#pragma unroll
        for (int kw = 0; kw < 8; kw++) {
            float2 v = rv[wp * RED_STRIDE + kw * 32 + lane];
            s0 += v.x; s1 += v.y;
        }
        g_hyW[(size_t)b0 * Hn + h] = s0;
        g_hyW[(size_t)b1 * Hn + h] = s1;
    }
}

// ---------------- spiking phase + tail broadcast (float2, 32K threads) ----------------
__global__ void spike_kernel(float* __restrict__ out) {
    int idx = blockIdx.x * blockDim.x + threadIdx.x;   // 0 .. B*H/2-1
    int b  = idx >> 9;
    int h2 = (idx & 511) * 2;

    float2 hyw = reinterpret_cast<const float2*>(g_hyW)[idx];
    float2 hyf = reinterpret_cast<const float2*>(g_hyfin)[idx];
    float2 hzf = reinterpret_cast<const float2*>(g_hzfin)[idx];
    float2 u = make_float2(0.f, 0.f);

    float* hys = out;
    float* hzs = out + (size_t)Bn * Tn * Hn;
    float* us  = out + (size_t)2 * Bn * Tn * Hn;
    float* sp  = us  + (size_t)Bn * TSp * Hn;

    const float* Pb = g_P + (size_t)b * THm * Hn + h2;
    size_t o_us = (size_t)b * TSp * Hn + h2;
    size_t o_hy = ((size_t)b * Tn + THm) * Hn + h2;
    const float k = 0.025f * 0.042f;

#pragma unroll 4
    for (int t = 0; t < TSp; t++) {
        float2 s;
        s.x = (u.x > 0.008f) ? 1.f : 0.f;  if (s.x != 0.f) u.x = 0.001f;
        s.y = (u.y > 0.008f) ? 1.f : 0.f;  if (s.y != 0.f) u.y = 0.001f;
        float2 p = __ldcs(reinterpret_cast<const float2*>(Pb + (size_t)t * Hn));
        u.x += (-u.x + hyw.x + p.x) * k;
        u.y += (-u.y + hyw.y + p.y) * k;
        __stcs(reinterpret_cast<float2*>(us  + o_us), u);
        __stcs(reinterpret_cast<float2*>(sp  + o_us), s);
        __stcs(reinterpret_cast<float2*>(hys + o_hy), hyf);
        __stcs(reinterpret_cast<float2*>(hzs + o_hy), hzf);
        o_us += Hn;
        o_hy += Hn;
    }
}

// ---------------- launch ----------------
extern "C" void kernel_launch(void* const* d_in, const int* in_sizes, int n_in,
                              void* d_out, int out_size) {
    const float* x    = (const float*)d_in[0];
    const float* x2h  = (const float*)d_in[1];
    const float* h2h  = (const float*)d_in[2];
    const float* bias = (const float*)d_in[3];
    const float* gvec = (const float*)d_in[4];
    const float* evec = (const float*)d_in[5];
    float* out = (float*)d_out;

    const int harm_smem = (32 * Hn) * 4 + 8 * PAIR_STRIDE * 16 + 8 * RED_STRIDE * 8;
    const int p_smem    = (32 * Hn + 64 * NI) * (int)sizeof(float);  // 144 KB
    cudaFuncSetAttribute(harm_kernel, cudaFuncAttributeMaxDynamicSharedMemorySize, harm_smem);
    cudaFuncSetAttribute(p_kernel, cudaFuncAttributeMaxDynamicSharedMemorySize, p_smem);

    float* hys = out;
    float* hzs = out + (size_t)Bn * Tn * Hn;

    init_kernel<<<1, 128>>>();
    p_kernel<<<dim3(4, 64), 256, p_smem>>>(x, x2h);
    harm_kernel<<<NCTA, 256, harm_smem>>>(h2h, bias, gvec, evec, hys, hzs);
    spike_kernel<<<Bn * Hn / 2 / 128, 128>>>(out);
}

// round 16
// speedup vs baseline: 1.5842x; 1.0388x over previous
#include <cuda_runtime.h>
#include <math.h>

#define Bn   64
#define Tn   512
#define NI   64
#define Hn   1024
#define THm  256     // T_HARM
#define TSp  256     // T_SPIKE
#define NCTA 128     // 32 h-groups x 4 batch-groups
#define DT_F 0.042f

#define PAIR_STRIDE 513    // float4 units per hyP pair block (512 + 1 pad)
#define RED_STRIDE  257    // ull units per red pair block (8*32 + 1 pad)

// packed fp32x2 helpers (FFMA2 — only reachable via PTX)
#define FMA2(acc, a, b) asm("fma.rn.f32x2 %0, %1, %2, %0;" : "+l"(acc) : "l"(a), "l"(b))
#define DUP2(d, f)      asm("mov.b64 %0, {%1, %1};" : "=l"(d) : "r"(__float_as_uint(f)))
#define UNPK2(lo, hi, v) asm("mov.b64 {%0, %1}, %2;" : "=f"(lo), "=f"(hi) : "l"(v))

typedef unsigned long long ull;

// fast tanh: 1 - 2/(1 + e^{2x}) via MUFU (abs err ~1e-6; tolerance budget 1e-3)
__device__ __forceinline__ float fast_tanh(float x) {
    float e, r;
    asm("ex2.approx.f32 %0, %1;" : "=f"(e) : "f"(x * 2.88539008f));  // 2*log2(e)
    asm("rcp.approx.f32 %0, %1;" : "=f"(r) : "f"(1.f + e));
    return fmaf(-2.f, r, 1.f);
}

// ---------------- device scratch ----------------
__device__ float g_P[(size_t)Bn * THm * Hn];   // x[:, :256] @ x2h  (64 MB)
__device__ float g_hy[2][Bn * Hn];             // double-buffered recurrent state
__device__ float g_hyfin[Bn * Hn];
__device__ float g_hzfin[Bn * Hn];
__device__ float g_hyW[Bn * Hn];
__device__ unsigned g_count[4 * 32];           // one counter per group, 128B apart

__device__ __forceinline__ void arrive_release(unsigned* p) {
    asm volatile("red.release.gpu.global.add.u32 [%0], 1;" :: "l"(p) : "memory");
}
__device__ __forceinline__ unsigned ld_acquire(const unsigned* p) {
    unsigned v;
    asm volatile("ld.acquire.gpu.global.u32 %0, [%1];" : "=r"(v) : "l"(p) : "memory");
    return v;
}

// ---------------- init (must reset counters every replay) ----------------
__global__ void init_kernel() {
    int idx = threadIdx.x + blockIdx.x * blockDim.x;
    if (idx < 128) g_count[idx] = 0u;
}

// ---------------- P = x[:, :256] @ x2h  (tiled, FFMA2) ----------------
__global__ void __launch_bounds__(256, 1) p_kernel(
    const float* __restrict__ x, const float* __restrict__ x2h)
{
    extern __shared__ float ps[];
    float* x2hS = ps;             // 32*1024
    float* xS   = ps + 32 * Hn;   // 64*64

    const int tid = threadIdx.x;
    const int tc  = blockIdx.x;
    const int b   = blockIdx.y;

    {
        const float4* src = reinterpret_cast<const float4*>(x + ((size_t)b * Tn + tc * 64) * NI);
        float4* dst = reinterpret_cast<float4*>(xS);
#pragma unroll
        for (int i = 0; i < 4; i++) dst[tid + 256 * i] = src[tid + 256 * i];
    }

    float* Pout = g_P + ((size_t)b * THm + tc * 64) * Hn + tid * 4;
    const ulonglong2* wv = reinterpret_cast<const ulonglong2*>(x2hS);

    for (int kc = 0; kc < 2; kc++) {
        {
            const float4* src = reinterpret_cast<const float4*>(x2h + (size_t)kc * 32 * Hn);
            float4* dst = reinterpret_cast<float4*>(x2hS);
#pragma unroll
            for (int i = 0; i < 32; i++) dst[tid + 256 * i] = src[tid + 256 * i];
        }
        __syncthreads();

        for (int t = 0; t < 64; t++) {
            ull acc0 = 0ull, acc1 = 0ull;
            const float* xr = xS + t * NI + kc * 32;
#pragma unroll 8
            for (int k = 0; k < 32; k++) {
                ull xb; DUP2(xb, xr[k]);
                ulonglong2 w = wv[k * 256 + tid];
                FMA2(acc0, w.x, xb);
                FMA2(acc1, w.y, xb);
            }
            float4 r;
            UNPK2(r.x, r.y, acc0);
            UNPK2(r.z, r.w, acc1);
            float4* po = reinterpret_cast<float4*>(Pout + (size_t)t * Hn);
            if (kc == 1) {
                float4 prev = *po;
                r.x += prev.x; r.y += prev.y; r.z += prev.z; r.w += prev.w;
            }
            *po = r;
        }
        __syncthreads();
    }
}

// ---------------- harmonic persistent scan (full range, merged) ----------------
// 128 CTAs x 256 threads.  CTA (hb, bb): 32 h x 16 batches.
// GEMM: thread tile 4h x 4b: lane -> (q = lane&7 h-quad, g = lane>>3 b-group);
//       warp wp owns k range [wp*128, wp*128+128).
// Wt2[k][h] identity h-major (128KB).  hyP pair-interleaved, pair stride 513 float4.
// Update: warp wp owns pair wp.  Barrier: per-group monotonic counter, warp 0 polls.
__global__ void __launch_bounds__(256, 1) harm_kernel(
    const float* __restrict__ h2h, const float* __restrict__ bias,
    const float* __restrict__ gvec, const float* __restrict__ evec,
    float* __restrict__ hys, float* __restrict__ hzs)
{
    extern __shared__ float smem[];
    float* Wt  = smem;                         // 32768 floats (Wt2[k][32h])
    float* hyP = smem + 32 * Hn;               // 8 * 513 float4
    float* red = smem + 32 * Hn + 8 * PAIR_STRIDE * 4;  // 8 * 257 ull

    const int tid  = threadIdx.x;
    const int lane = tid & 31;
    const int wp   = tid >> 5;
    const int hb   = blockIdx.x & 31;
    const int bb   = blockIdx.x >> 5;
    const int h    = hb * 32 + lane;
    const int q    = lane & 7;                 // h-quad
    const int g    = lane >> 3;                // b-group
    unsigned* cnt  = &g_count[bb * 32];

    // ---- stage W identity h-major: Wt2[k*32 .. k*32+31] = h2h[k][hb*32 ..+31] ----
    {
        const int r4 = lane >> 3;
        float4* Wt4 = reinterpret_cast<float4*>(Wt);
#pragma unroll 4
        for (int i2 = 0; i2 < 32; i2++) {
            int k = wp * 128 + i2 * 4 + r4;
            Wt4[k * 8 + q] =
                *(reinterpret_cast<const float4*>(h2h + (size_t)k * Hn + hb * 32) + q);
        }
    }

    const float gy = gvec[h];
    const float ge = evec[h];
    const float bi = bias[h];

    const int b0 = bb * 16 + 2 * wp;
    const int b1 = b0 + 1;
    float hy0 = 0.f, hy1 = 0.f, hz0 = 0.f, hz1 = 0.f;
    float pv0 = __ldcs(&g_P[(size_t)b0 * THm * Hn + h]);
    float pv1 = __ldcs(&g_P[(size_t)b1 * THm * Hn + h]);

    const float4* wrow = reinterpret_cast<const float4*>(Wt) + q;             // + k*8
    const ulonglong2* hvE = reinterpret_cast<const ulonglong2*>(hyP) + (size_t)(2 * g) * PAIR_STRIDE;
    const ulonglong2* hvO = hvE + PAIR_STRIDE;
    ull* redu = reinterpret_cast<ull*>(red);
    const int red_w = wp * 32 + 4 * q;        // + hh, within pair block
    __syncthreads();

    for (int t = 0; t < THm; t++) {
        if (t > 0) {
            // warp 0 polls for all 256 warps of this group; others wait at barrier
            if (wp == 0) {
                unsigned want = (unsigned)t << 8;
                while (ld_acquire(cnt) < want) { }
            }
            __syncthreads();

            // ---- stage hy pair wp (pair-interleaved, padded block) ----
            {
                const float* buf = g_hy[t & 1];
                const float4* r0 = reinterpret_cast<const float4*>(buf + (size_t)b0 * Hn);
                const float4* r1 = reinterpret_cast<const float4*>(buf + (size_t)b1 * Hn);
                float4* dst = reinterpret_cast<float4*>(hyP) + (size_t)wp * PAIR_STRIDE;
                float4 ra[8], rc[8];
#pragma unroll
                for (int i = 0; i < 8; i++) {
                    ra[i] = __ldcg(r0 + lane + i * 32);
                    rc[i] = __ldcg(r1 + lane + i * 32);
                }
#pragma unroll
                for (int i = 0; i < 8; i++) {
                    dst[64 * i + lane]      = make_float4(ra[i].x, rc[i].x, ra[i].y, rc[i].y);
                    dst[64 * i + 32 + lane] = make_float4(ra[i].z, rc[i].z, ra[i].w, rc[i].w);
                }
            }
            __syncthreads();

            // ---- GEMM: 4h x 4b thread tile, warp k range [wp*128, +128) ----
            ull acc[4][2];
#pragma unroll
            for (int hh = 0; hh < 4; hh++) { acc[hh][0] = 0ull; acc[hh][1] = 0ull; }
            const int base = wp * 64;
#pragma unroll 4
            for (int t2 = 0; t2 < 32; t2++) {
                ulonglong2 aE = hvE[base + t2];        // pair 2g,   k=4k4,4k4+1
                ulonglong2 cE = hvE[base + t2 + 32];   // pair 2g,   k=4k4+2,+3
                ulonglong2 aO = hvO[base + t2];        // pair 2g+1
                ulonglong2 cO = hvO[base + t2 + 32];
                const int k = (wp * 32 + t2) * 4;
                float4 w0 = wrow[(k + 0) * 8];
                float4 w1 = wrow[(k + 1) * 8];
                float4 w2 = wrow[(k + 2) * 8];
                float4 w3 = wrow[(k + 3) * 8];
#pragma unroll
                for (int hh = 0; hh < 4; hh++) {
                    ull dw0, dw1, dw2, dw3;
                    DUP2(dw0, (&w0.x)[hh]);
                    DUP2(dw1, (&w1.x)[hh]);
                    DUP2(dw2, (&w2.x)[hh]);
                    DUP2(dw3, (&w3.x)[hh]);
                    FMA2(acc[hh][0], aE.x, dw0); FMA2(acc[hh][0], aE.y, dw1);
                    FMA2(acc[hh][0], cE.x, dw2); FMA2(acc[hh][0], cE.y, dw3);
                    FMA2(acc[hh][1], aO.x, dw0); FMA2(acc[hh][1], aO.y, dw1);
                    FMA2(acc[hh][1], cO.x, dw2); FMA2(acc[hh][1], cO.y, dw3);
                }
            }
#pragma unroll
            for (int hh = 0; hh < 4; hh++) {
                redu[(2 * g + 0) * RED_STRIDE + red_w + hh] = acc[hh][0];
                redu[(2 * g + 1) * RED_STRIDE + red_w + hh] = acc[hh][1];
            }
        }
        __syncthreads();

        // ---- update: warp wp owns pair (b0, b1) ----
        float s0 = 0.f, s1 = 0.f;
        if (t > 0) {
            const float2* rv = reinterpret_cast<const float2*>(red);
#pragma unroll
            for (int kw = 0; kw < 8; kw++) {
                float2 v = rv[wp * RED_STRIDE + kw * 32 + lane];
                s0 += v.x; s1 += v.y;
            }
        }
        float th0 = fast_tanh(s0 + pv0 + bi);
        float th1 = fast_tanh(s1 + pv1 + bi);
        hz0 = hz0 + DT_F * (th0 - gy * hy0 - ge * hz0);
        hy0 = hy0 + DT_F * hz0;
        hz1 = hz1 + DT_F * (th1 - gy * hy1 - ge * hz1);
        hy1 = hy1 + DT_F * hz1;

        // state into buffer (t+1)&1, then per-warp release arrival
        float* bufn = g_hy[(t + 1) & 1];
        bufn[(size_t)b0 * Hn + h] = hy0;
        bufn[(size_t)b1 * Hn + h] = hy1;
        if (lane == 0) arrive_release(cnt);

        // next P prefetch (streaming loads first), then streaming trajectory stores
        if (t + 1 < THm) {
            pv0 = __ldcs(&g_P[((size_t)b0 * THm + t + 1) * Hn + h]);
            pv1 = __ldcs(&g_P[((size_t)b1 * THm + t + 1) * Hn + h]);
        }
        __stcs(&hys[((size_t)b0 * Tn + t) * Hn + h], hy0);
        __stcs(&hys[((size_t)b1 * Tn + t) * Hn + h], hy1);
        __stcs(&hzs[((size_t)b0 * Tn + t) * Hn + h], hz0);
        __stcs(&hzs[((size_t)b1 * Tn + t) * Hn + h], hz1);
    }

    // ---- finals ----
    g_hyfin[(size_t)b0 * Hn + h] = hy0;
    g_hyfin[(size_t)b1 * Hn + h] = hy1;
    g_hzfin[(size_t)b0 * Hn + h] = hz0;
    g_hzfin[(size_t)b1 * Hn + h] = hz1;

    // ---- hyW = hy_fin @ W ----
    {
        if (wp == 0) {
            unsigned want = (unsigned)THm << 8;
            while (ld_acquire(cnt) < want) { }
        }
        __syncthreads();
        const float* buf = g_hy[THm & 1];
        const float4* r0 = reinterpret_cast<const float4*>(buf + (size_t)b0 * Hn);
        const float4* r1 = reinterpret_cast<const float4*>(buf + (size_t)b1 * Hn);
        float4* dst = reinterpret_cast<float4*>(hyP) + (size_t)wp * PAIR_STRIDE;
        float4 ra[8], rc[8];
#pragma unroll
        for (int i = 0; i < 8; i++) {
            ra[i] = __ldcg(r0 + lane + i * 32);
            rc[i] = __ldcg(r1 + lane + i * 32);
        }
#pragma unroll
        for (int i = 0; i < 8; i++) {
            dst[64 * i + lane]      = make_float4(ra[i].x, rc[i].x, ra[i].y, rc[i].y);
            dst[64 * i + 32 + lane] = make_float4(ra[i].z, rc[i].z, ra[i].w, rc[i].w);
        }
    }
    __syncthreads();
    {
        ull acc[4][2];
#pragma unroll
        for (int hh = 0; hh < 4; hh++) { acc[hh][0] = 0ull; acc[hh][1] = 0ull; }
        const int base = wp * 64;
#pragma unroll 4
        for (int t2 = 0; t2 < 32; t2++) {
            ulonglong2 aE = hvE[base + t2];
            ulonglong2 cE = hvE[base + t2 + 32];
            ulonglong2 aO = hvO[base + t2];
            ulonglong2 cO = hvO[base + t2 + 32];
            const int k = (wp * 32 + t2) * 4;
            float4 w0 = wrow[(k + 0) * 8];
            float4 w1 = wrow[(k + 1) * 8];
            float4 w2 = wrow[(k + 2) * 8];
            float4 w3 = wrow[(k + 3) * 8];
#pragma unroll
            for (int hh = 0; hh < 4; hh++) {
                ull dw0, dw1, dw2, dw3;
                DUP2(dw0, (&w0.x)[hh]);
                DUP2(dw1, (&w1.x)[hh]);
                DUP2(dw2, (&w2.x)[hh]);
                DUP2(dw3, (&w3.x)[hh]);
                FMA2(acc[hh][0], aE.x, dw0); FMA2(acc[hh][0], aE.y, dw1);
                FMA2(acc[hh][0], cE.x, dw2); FMA2(acc[hh][0], cE.y, dw3);
                FMA2(acc[hh][1], aO.x, dw0); FMA2(acc[hh][1], aO.y, dw1);
                FMA2(acc[hh][1], cO.x, dw2); FMA2(acc[hh][1], cO.y, dw3);
            }
        }
#pragma unroll
        for (int hh = 0; hh < 4; hh++) {
            redu[(2 * g + 0) * RED_STRIDE + red_w + hh] = acc[hh][0];
            redu[(2 * g + 1) * RED_STRIDE + red_w + hh] = acc[hh][1];
        }
    }
    __syncthreads();
    {
        const float2* rv = reinterpret_cast<const float2*>(red);
        float s0 = 0.f, s1 = 0.f;
#pragma unroll
        for (int kw = 0; kw < 8; kw++) {
            float2 v = rv[wp * RED_STRIDE + kw * 32 + lane];
            s0 += v.x; s1 += v.y;
        }
        g_hyW[(size_t)b0 * Hn + h] = s0;
        g_hyW[(size_t)b1 * Hn + h] = s1;
    }
}

// ---------------- spiking phase + tail broadcast (float2, plain accesses) ----------------
__global__ void spike_kernel(float* __restrict__ out) {
    int idx = blockIdx.x * blockDim.x + threadIdx.x;   // 0 .. B*H/2-1
    int b  = idx >> 9;
    int h2 = (idx & 511) * 2;

    float2 hyw = reinterpret_cast<const float2*>(g_hyW)[idx];
    float2 hyf = reinterpret_cast<const float2*>(g_hyfin)[idx];
    float2 hzf = reinterpret_cast<const float2*>(g_hzfin)[idx];
    float2 u = make_float2(0.f, 0.f);

    float* hys = out;
    float* hzs = out + (size_t)Bn * Tn * Hn;
    float* us  = out + (size_t)2 * Bn * Tn * Hn;
    float* sp  = us  + (size_t)Bn * TSp * Hn;

    const float* Pb = g_P + (size_t)b * THm * Hn + h2;
    size_t o_us = (size_t)b * TSp * Hn + h2;
    size_t o_hy = ((size_t)b * Tn + THm) * Hn + h2;
    const float k = 0.025f * 0.042f;

#pragma unroll 4
    for (int t = 0; t < TSp; t++) {
        float2 s;
        s.x = (u.x > 0.008f) ? 1.f : 0.f;  if (s.x != 0.f) u.x = 0.001f;
        s.y = (u.y > 0.008f) ? 1.f : 0.f;  if (s.y != 0.f) u.y = 0.001f;
        float2 p = *reinterpret_cast<const float2*>(Pb + (size_t)t * Hn);
        u.x += (-u.x + hyw.x + p.x) * k;
        u.y += (-u.y + hyw.y + p.y) * k;
        *reinterpret_cast<float2*>(us  + o_us) = u;
        *reinterpret_cast<float2*>(sp  + o_us) = s;
        *reinterpret_cast<float2*>(hys + o_hy) = hyf;
        *reinterpret_cast<float2*>(hzs + o_hy) = hzf;
        o_us += Hn;
        o_hy += Hn;
    }
}

// ---------------- launch ----------------
extern "C" void kernel_launch(void* const* d_in, const int* in_sizes, int n_in,
                              void* d_out, int out_size) {
    const float* x    = (const float*)d_in[0];
    const float* x2h  = (const float*)d_in[1];
    const float* h2h  = (const float*)d_in[2];
    const float* bias = (const float*)d_in[3];
    const float* gvec = (const float*)d_in[4];
    const float* evec = (const float*)d_in[5];
    float* out = (float*)d_out;

    const int harm_smem = (32 * Hn) * 4 + 8 * PAIR_STRIDE * 16 + 8 * RED_STRIDE * 8;
    const int p_smem    = (32 * Hn + 64 * NI) * (int)sizeof(float);  // 144 KB
    cudaFuncSetAttribute(harm_kernel, cudaFuncAttributeMaxDynamicSharedMemorySize, harm_smem);
    cudaFuncSetAttribute(p_kernel, cudaFuncAttributeMaxDynamicSharedMemorySize, p_smem);

    float* hys = out;
    float* hzs = out + (size_t)Bn * Tn * Hn;

    init_kernel<<<1, 128>>>();
    p_kernel<<<dim3(4, 64), 256, p_smem>>>(x, x2h);
    harm_kernel<<<NCTA, 256, harm_smem>>>(h2h, bias, gvec, evec, hys, hzs);
    spike_kernel<<<Bn * Hn / 2 / 128, 128>>>(out);
}